// round 15
// baseline (speedup 1.0000x reference)
#include <cuda_runtime.h>
#include <cuda_bf16.h>
#include <cstdint>

// Problem constants
constexpr int B_  = 2;
constexpr int L_  = 256;
constexpr int D_  = 4096;
constexpr int H_  = 32;
constexpr int Dh_ = 128;
constexpr int S_  = 4224;
constexpr int SINK_ = 128;
constexpr int WINS_ = S_ - L_;     // 3968
constexpr int M_  = B_ * L_;       // 512
constexpr size_t DD = (size_t)D_ * D_;
constexpr size_t CACHE_E = (size_t)B_ * S_ * H_ * Dh_;

// GEMM tiling
constexpr int BK = 32;
constexpr int NCHUNK = D_ / BK;        // 128
constexpr int A_ROW_B = 80;
constexpr int B_ROW_B = 272;
constexpr int A_TILE = 128 * A_ROW_B;  // 10240
constexpr int B_TILE = BK * B_ROW_B;   // 8704
constexpr int STAGE  = 2 * A_TILE + 2 * B_TILE;  // 37888
constexpr int SMEMT  = 2 * STAGE;      // 75776

// Attention smem: 64 q rows, 32-key tiles, double-buffered, 4 components
constexpr int ARB = 272;
constexpr int AQ_COMP = 64 * ARB;              // 17408
constexpr int AT_COMP = 32 * ARB;              // 8704
constexpr int AT_STG  = 4 * AT_COMP;           // 34816
constexpr int ATT_SMEM = 2 * AQ_COMP + 2 * AT_STG;  // 104448

// scratch
__device__ float g_q[M_ * D_];     // Q fp32; reused as split-K partial 0
__device__ float g_k[M_ * D_];     // K fp32; reused as split-K partial 1
__device__ float g_v[M_ * D_];
__device__ __nv_bfloat16 g_whi[4 * DD];
__device__ __nv_bfloat16 g_wlo[4 * DD];
__device__ __nv_bfloat16 g_xhi[M_ * D_];   // x split; reused for Q split
__device__ __nv_bfloat16 g_xlo[M_ * D_];
__device__ __nv_bfloat16 g_ohi[M_ * D_];
__device__ __nv_bfloat16 g_olo[M_ * D_];
__device__ __nv_bfloat16 g_ckhi[CACHE_E];
__device__ __nv_bfloat16 g_cklo[CACHE_E];
__device__ __nv_bfloat16 g_cvhi[CACHE_E];
__device__ __nv_bfloat16 g_cvlo[CACHE_E];
__device__ __nv_bfloat16 g_nkhi[M_ * D_];
__device__ __nv_bfloat16 g_nklo[M_ * D_];
__device__ __nv_bfloat16 g_nvhi[M_ * D_];
__device__ __nv_bfloat16 g_nvlo[M_ * D_];

// ---- helpers ----
__device__ __forceinline__ uint32_t smem_u32(const void* p) {
    uint32_t a;
    asm("{ .reg .u64 t; cvta.to.shared.u64 t, %1; cvt.u32.u64 %0, t; }" : "=r"(a) : "l"(p));
    return a;
}
__device__ __forceinline__ void ldsm4(uint32_t* r, uint32_t a) {
    asm volatile("ldmatrix.sync.aligned.m8n8.x4.shared.b16 {%0,%1,%2,%3},[%4];"
                 : "=r"(r[0]), "=r"(r[1]), "=r"(r[2]), "=r"(r[3]) : "r"(a));
}
__device__ __forceinline__ void ldsm4t(uint32_t* r, uint32_t a) {
    asm volatile("ldmatrix.sync.aligned.m8n8.x4.trans.shared.b16 {%0,%1,%2,%3},[%4];"
                 : "=r"(r[0]), "=r"(r[1]), "=r"(r[2]), "=r"(r[3]) : "r"(a));
}
__device__ __forceinline__ void mma_bf(float* c, const uint32_t* a, uint32_t b0, uint32_t b1) {
    asm volatile(
        "mma.sync.aligned.m16n8k16.row.col.f32.bf16.bf16.f32 "
        "{%0,%1,%2,%3},{%4,%5,%6,%7},{%8,%9},{%0,%1,%2,%3};"
        : "+f"(c[0]), "+f"(c[1]), "+f"(c[2]), "+f"(c[3])
        : "r"(a[0]), "r"(a[1]), "r"(a[2]), "r"(a[3]), "r"(b0), "r"(b1));
}
// packed split: rn rounding, bit-identical to scalar __float2bfloat16_rn path.
__device__ __forceinline__ void split2(float x, float y, uint32_t& hi, uint32_t& lo) {
    uint32_t h;
    asm("cvt.rn.bf16x2.f32 %0, %1, %2;" : "=r"(h) : "f"(y), "f"(x));
    float hx = __uint_as_float(h << 16);
    float hy = __uint_as_float(h & 0xffff0000u);
    float lx = x - hx;
    float ly = y - hy;
    uint32_t l;
    asm("cvt.rn.bf16x2.f32 %0, %1, %2;" : "=r"(l) : "f"(ly), "f"(lx));
    hi = h; lo = l;
}
__device__ __forceinline__ void cpa16(uint32_t dst, const void* src) {
    asm volatile("cp.async.ca.shared.global [%0],[%1],16;" :: "r"(dst), "l"(src));
}
__device__ __forceinline__ void cpa_commit() {
    asm volatile("cp.async.commit_group;" ::: "memory");
}
__device__ __forceinline__ void cpa_wait1() {
    asm volatile("cp.async.wait_group 1;" ::: "memory");
}
__device__ __forceinline__ void cpa_wait0() {
    asm volatile("cp.async.wait_group 0;" ::: "memory");
}

// ---------------------------------------------------------------------------
// Split-convert kernels (serial execution — no stream overlap: co-scheduling
// DRAM-bound converts with the GEMM poisons its cp.async pipeline; R14 data)
// ---------------------------------------------------------------------------
__global__ __launch_bounds__(256) void cvt_x(
    const float* __restrict__ src,
    __nv_bfloat16* __restrict__ hi, __nv_bfloat16* __restrict__ lo)
{
    const size_t i = ((size_t)blockIdx.x * 256 + threadIdx.x) * 8;
    float4 f0 = *(const float4*)(src + i);
    float4 f1 = *(const float4*)(src + i + 4);
    uint4 h, l;
    split2(f0.x, f0.y, h.x, l.x);
    split2(f0.z, f0.w, h.y, l.y);
    split2(f1.x, f1.y, h.z, l.z);
    split2(f1.z, f1.w, h.w, l.w);
    *(uint4*)(hi + i) = h;
    *(uint4*)(lo + i) = l;
}

__global__ __launch_bounds__(256) void cvt_w(
    const float* __restrict__ w0, const float* __restrict__ w1,
    const float* __restrict__ w2, const float* __restrict__ w3,
    __nv_bfloat16* __restrict__ hi, __nv_bfloat16* __restrict__ lo)
{
    const float* src = (blockIdx.y == 0) ? w0 : (blockIdx.y == 1) ? w1
                     : (blockIdx.y == 2) ? w2 : w3;
    const size_t base = (size_t)blockIdx.y * DD;
    const size_t i = ((size_t)blockIdx.x * 256 + threadIdx.x) * 8;
    float4 f0 = *(const float4*)(src + i);
    float4 f1 = *(const float4*)(src + i + 4);
    uint4 h, l;
    split2(f0.x, f0.y, h.x, l.x);
    split2(f0.z, f0.w, h.y, l.y);
    split2(f1.x, f1.y, h.z, l.z);
    split2(f1.z, f1.w, h.w, l.w);
    *(uint4*)(hi + base + i) = h;
    *(uint4*)(lo + base + i) = l;
}

// out = a + b (fp32, vectorized) — split-K reduction
__global__ __launch_bounds__(256) void add2(const float* __restrict__ a,
                                            const float* __restrict__ b,
                                            float* __restrict__ out) {
    const size_t i = ((size_t)blockIdx.x * 256 + threadIdx.x) * 4;
    float4 x = *(const float4*)(a + i);
    float4 y = *(const float4*)(b + i);
    *(float4*)(out + i) = make_float4(x.x + y.x, x.y + y.y, x.z + y.z, x.w + y.w);
}

// ---------------------------------------------------------------------------
// mma.sync split-bf16 GEMM. splitk=0: blockIdx.z selects (weight, C), full K.
// splitk=1: weight fixed at wzoff, blockIdx.z selects K-half and partial C.
// ---------------------------------------------------------------------------
__global__ __launch_bounds__(256, 2) void gemm_mma(
    const __nv_bfloat16* __restrict__ Ahi, const __nv_bfloat16* __restrict__ Alo,
    const __nv_bfloat16* __restrict__ Whi, const __nv_bfloat16* __restrict__ Wlo,
    int wzoff, int splitk,
    float* __restrict__ C0, float* __restrict__ C1, float* __restrict__ C2)
{
    const int z = blockIdx.z;
    float* C = (z == 0) ? C0 : (z == 1) ? C1 : C2;
    const size_t woff = (size_t)(splitk ? wzoff : wzoff + z) * DD;
    const int kbeg = splitk ? z * (NCHUNK / 2) : 0;
    const int nch  = splitk ? (NCHUNK / 2) : NCHUNK;

    extern __shared__ char smem[];
    const uint32_t sb = smem_u32(smem);
    const int tid  = threadIdx.x;
    const int wid  = tid >> 5;
    const int lane = tid & 31;
    const int wm   = wid & 1;
    const int wn   = wid >> 1;

    const int m0 = blockIdx.y * 128;
    const int n0 = blockIdx.x * 128;

    const __nv_bfloat16* AhiB = Ahi + (size_t)m0 * D_;
    const __nv_bfloat16* AloB = Alo + (size_t)m0 * D_;
    const __nv_bfloat16* WhiB = Whi + woff + n0;
    const __nv_bfloat16* WloB = Wlo + woff + n0;

    float acc[4][4][4];
#pragma unroll
    for (int mt = 0; mt < 4; ++mt)
#pragma unroll
        for (int nt = 0; nt < 4; ++nt)
#pragma unroll
            for (int e = 0; e < 4; ++e) acc[mt][nt][e] = 0.0f;

    const int a_r   = (lane & 7) + ((lane >> 3) & 1) * 8;
    const int a_kb  = (lane >> 4) * 16;
    const int b_kr  = (lane & 7) + (lane >> 4) * 8;
    const int b_nb  = ((lane >> 3) & 1) * 16;

    auto issue_stage = [&](int ch, int s) {
        const uint32_t stA = sb + s * STAGE;
        const uint32_t stB = stA + 2 * A_TILE;
#pragma unroll
        for (int i = 0; i < 2; ++i) {
            const int c = tid * 2 + i;
            const int ar = c >> 2, akc = c & 3;
            const size_t aoff = (size_t)ar * D_ + ch * BK + akc * 8;
            const uint32_t adst = stA + ar * A_ROW_B + akc * 16;
            cpa16(adst, AhiB + aoff);
            cpa16(adst + A_TILE, AloB + aoff);
            const int br = c >> 4, bnc = c & 15;
            const size_t boff = (size_t)(ch * BK + br) * D_ + bnc * 8;
            const uint32_t bdst = stB + br * B_ROW_B + bnc * 16;
            cpa16(bdst, WhiB + boff);
            cpa16(bdst + B_TILE, WloB + boff);
        }
        cpa_commit();
    };

    issue_stage(kbeg, 0);

    for (int ci = 0; ci < nch; ++ci) {
        const int s = ci & 1;
        if (ci + 1 < nch) { issue_stage(kbeg + ci + 1, s ^ 1); cpa_wait1(); }
        else cpa_wait0();
        __syncthreads();

        const uint32_t Ah = sb + s * STAGE;
        const uint32_t Al = Ah + A_TILE;
        const uint32_t Bh = Ah + 2 * A_TILE;
        const uint32_t Bl = Bh + B_TILE;

#pragma unroll
        for (int kc = 0; kc < 2; ++kc) {
            uint32_t ah[4][4], al[4][4];
            uint32_t bh[4][2], bl[4][2];
            const uint32_t a_addr = (uint32_t)((wm * 64 + a_r) * A_ROW_B + kc * 32 + a_kb);
#pragma unroll
            for (int mt = 0; mt < 4; ++mt) {
                ldsm4(ah[mt], Ah + a_addr + mt * 16 * A_ROW_B);
                ldsm4(al[mt], Al + a_addr + mt * 16 * A_ROW_B);
            }
            const uint32_t b_addr = (uint32_t)((kc * 16 + b_kr) * B_ROW_B + (wn * 32) * 2 + b_nb);
#pragma unroll
            for (int p = 0; p < 2; ++p) {
                uint32_t rh[4], rl[4];
                ldsm4t(rh, Bh + b_addr + p * 32);
                ldsm4t(rl, Bl + b_addr + p * 32);
                bh[2 * p][0] = rh[0]; bh[2 * p][1] = rh[2];
                bh[2 * p + 1][0] = rh[1]; bh[2 * p + 1][1] = rh[3];
                bl[2 * p][0] = rl[0]; bl[2 * p][1] = rl[2];
                bl[2 * p + 1][0] = rl[1]; bl[2 * p + 1][1] = rl[3];
            }
#pragma unroll
            for (int mt = 0; mt < 4; ++mt)
#pragma unroll
                for (int nt = 0; nt < 4; ++nt)
                    mma_bf(acc[mt][nt], ah[mt], bh[nt][0], bh[nt][1]);
#pragma unroll
            for (int mt = 0; mt < 4; ++mt)
#pragma unroll
                for (int nt = 0; nt < 4; ++nt)
                    mma_bf(acc[mt][nt], ah[mt], bl[nt][0], bl[nt][1]);
#pragma unroll
            for (int mt = 0; mt < 4; ++mt)
#pragma unroll
                for (int nt = 0; nt < 4; ++nt)
                    mma_bf(acc[mt][nt], al[mt], bh[nt][0], bh[nt][1]);
        }
        __syncthreads();
    }

    const int gr = lane >> 2;
    const int gc = lane & 3;
#pragma unroll
    for (int mt = 0; mt < 4; ++mt) {
        const int row = m0 + wm * 64 + mt * 16 + gr;
        float* c0 = C + (size_t)row * D_ + n0 + wn * 32;
        float* c1 = C + (size_t)(row + 8) * D_ + n0 + wn * 32;
#pragma unroll
        for (int nt = 0; nt < 4; ++nt) {
            *(float2*)(c0 + nt * 8 + gc * 2) = make_float2(acc[mt][nt][0], acc[mt][nt][1]);
            *(float2*)(c1 + nt * 8 + gc * 2) = make_float2(acc[mt][nt][2], acc[mt][nt][3]);
        }
    }
}

// ---------------------------------------------------------------------------
// rmsnorm + split + pre-scale (Q)
// ---------------------------------------------------------------------------
__global__ __launch_bounds__(256) void rmsnorm_qsplit(const float* __restrict__ X,
                                                      const float* __restrict__ w,
                                                      __nv_bfloat16* __restrict__ hi,
                                                      __nv_bfloat16* __restrict__ lo) {
    const int row  = (blockIdx.x * 256 + threadIdx.x) >> 5;
    const int lane = threadIdx.x & 31;
    const float* p = X + (size_t)row * 128 + lane * 4;
    float4 v = *(const float4*)p;
    float ss = v.x * v.x + v.y * v.y + v.z * v.z + v.w * v.w;
#pragma unroll
    for (int o = 16; o; o >>= 1) ss += __shfl_xor_sync(0xffffffffu, ss, o);
    float r = rsqrtf(ss * (1.0f / 128.0f) + 1e-6f) * 0.08838834764831845f;
    float4 wv = *(const float4*)(w + lane * 4);
    v.x *= r * wv.x; v.y *= r * wv.y; v.z *= r * wv.z; v.w *= r * wv.w;
    uint32_t h0, l0, h1, l1;
    split2(v.x, v.y, h0, l0);
    split2(v.z, v.w, h1, l1);
    *(uint2*)(hi + (size_t)row * 128 + lane * 4) = make_uint2(h0, h1);
    *(uint2*)(lo + (size_t)row * 128 + lane * 4) = make_uint2(l0, l1);
}

// rmsnorm + split (K)
__global__ __launch_bounds__(256) void rmsnorm_split(const float* __restrict__ X,
                                                     const float* __restrict__ w,
                                                     __nv_bfloat16* __restrict__ hi,
                                                     __nv_bfloat16* __restrict__ lo) {
    const int row  = (blockIdx.x * 256 + threadIdx.x) >> 5;
    const int lane = threadIdx.x & 31;
    const float* p = X + (size_t)row * 128 + lane * 4;
    float4 v = *(const float4*)p;
    float ss = v.x * v.x + v.y * v.y + v.z * v.z + v.w * v.w;
#pragma unroll
    for (int o = 16; o; o >>= 1) ss += __shfl_xor_sync(0xffffffffu, ss, o);
    float r = rsqrtf(ss * (1.0f / 128.0f) + 1e-6f);
    float4 wv = *(const float4*)(w + lane * 4);
    v.x *= r * wv.x; v.y *= r * wv.y; v.z *= r * wv.z; v.w *= r * wv.w;
    uint32_t h0, l0, h1, l1;
    split2(v.x, v.y, h0, l0);
    split2(v.z, v.w, h1, l1);
    *(uint2*)(hi + (size_t)row * 128 + lane * 4) = make_uint2(h0, h1);
    *(uint2*)(lo + (size_t)row * 128 + lane * 4) = make_uint2(l0, l1);
}

// ---------------------------------------------------------------------------
// MMA flash attention (unchanged)
// ---------------------------------------------------------------------------
__global__ __launch_bounds__(256, 2) void attn_mma(
    const __nv_bfloat16* __restrict__ Qhi, const __nv_bfloat16* __restrict__ Qlo,
    const __nv_bfloat16* __restrict__ CKhi, const __nv_bfloat16* __restrict__ CKlo,
    const __nv_bfloat16* __restrict__ CVhi, const __nv_bfloat16* __restrict__ CVlo,
    const __nv_bfloat16* __restrict__ NKhi, const __nv_bfloat16* __restrict__ NKlo,
    const __nv_bfloat16* __restrict__ NVhi, const __nv_bfloat16* __restrict__ NVlo,
    __nv_bfloat16* __restrict__ Ohi, __nv_bfloat16* __restrict__ Olo)
{
    extern __shared__ char asmem[];
    const uint32_t sb = smem_u32(asmem);

    const int tid  = threadIdx.x;
    const int wid  = tid >> 5;
    const int lane = tid & 31;
    const int mg   = wid >> 1;
    const int sp   = wid & 1;
    const int h    = blockIdx.y;
    const int b    = blockIdx.z;
    const int q0   = blockIdx.x * 64;

    const uint32_t Qhi_o = sb;
    const uint32_t Qlo_o = sb + AQ_COMP;
    const uint32_t STG0  = sb + 2 * AQ_COMP;

    {
        const int row = tid >> 2;
        const int d0  = (tid & 3) * 32;
        const size_t src = ((size_t)(b * L_ + q0 + row) * H_ + h) * Dh_ + d0;
        const uint32_t dst = (uint32_t)(row * ARB + d0 * 2);
#pragma unroll
        for (int i = 0; i < 4; ++i) {
            cpa16(Qhi_o + dst + 16 * i, Qhi + src + 8 * i);
            cpa16(Qlo_o + dst + 16 * i, Qlo + src + 8 * i);
        }
    }

    const int a_r  = (lane & 7) + ((lane >> 3) & 1) * 8;
    const int a_kb = (lane >> 4) * 16;
    const int b_kr = (lane & 7) + (lane >> 4) * 8;
    const int b_nb = ((lane >> 3) & 1) * 16;

    float o[16][4];
#pragma unroll
    for (int nt = 0; nt < 16; ++nt)
#pragma unroll
        for (int e = 0; e < 4; ++e) o[nt][e] = 0.0f;
    float m0 = -1e30f, m1 = -1e30f, l0 = 0.0f, l1 = 0.0f;

    const int wlim = WINS_ + q0 + mg * 16;
    const int lim0 = wlim + (lane >> 2);
    const int lim1 = lim0 + 8;
    const int n_t  = (WINS_ + q0 + 64) / 32;

    auto issue_tile = [&](int t, int s) {
        const int sg = t * 32 + (tid >> 3);
        const __nv_bfloat16 *kh, *kl, *vh, *vl;
        if (sg < WINS_) {
            const int src = (sg < SINK_) ? sg : sg + L_;
            const size_t off = (((size_t)b * S_ + src) * H_ + h) * Dh_;
            kh = CKhi + off; kl = CKlo + off; vh = CVhi + off; vl = CVlo + off;
        } else {
            const size_t off = (((size_t)b * L_ + (sg - WINS_)) * H_ + h) * Dh_;
            kh = NKhi + off; kl = NKlo + off; vh = NVhi + off; vl = NVlo + off;
        }
        const uint32_t base = STG0 + s * AT_STG + (tid >> 3) * ARB;
#pragma unroll
        for (int i = 0; i < 2; ++i) {
            const int c16 = (tid & 7) * 2 + i;
            const uint32_t d = base + c16 * 16;
            cpa16(d, kh + c16 * 8);
            cpa16(d + AT_COMP, kl + c16 * 8);
            cpa16(d + 2 * AT_COMP, vh + c16 * 8);
            cpa16(d + 3 * AT_COMP, vl + c16 * 8);
        }
        cpa_commit();
    };

    issue_tile(0, 0);

    for (int t = 0; t < n_t; ++t) {
        const int s = t & 1;
        cpa_wait0();
        __syncthreads();
        if (t + 1 < n_t) issue_tile(t + 1, s ^ 1);

        const int colbase = t * 32 + sp * 16;
        if (colbase <= wlim + 15) {
            const uint32_t Khi_s = STG0 + s * AT_STG;
            const uint32_t Klo_s = Khi_s + AT_COMP;
            const uint32_t Vhi_s = Khi_s + 2 * AT_COMP;
            const uint32_t Vlo_s = Khi_s + 3 * AT_COMP;

            float sf[2][4];
#pragma unroll
            for (int nt = 0; nt < 2; ++nt)
#pragma unroll
                for (int e = 0; e < 4; ++e) sf[nt][e] = 0.0f;

#pragma unroll
            for (int ks = 0; ks < 8; ++ks) {
                const uint32_t qa = (uint32_t)((mg * 16 + a_r) * ARB + ks * 32 + a_kb);
                const uint32_t ka = (uint32_t)((sp * 16 + a_r) * ARB + ks * 32 + a_kb);
                uint32_t qh4[4], ql4[4], kh4[4], kl4[4];
                ldsm4(qh4, Qhi_o + qa);
                ldsm4(ql4, Qlo_o + qa);
                ldsm4(kh4, Khi_s + ka);
                ldsm4(kl4, Klo_s + ka);
                mma_bf(sf[0], qh4, kh4[0], kh4[2]);
                mma_bf(sf[1], qh4, kh4[1], kh4[3]);
                mma_bf(sf[0], qh4, kl4[0], kl4[2]);
                mma_bf(sf[1], qh4, kl4[1], kl4[3]);
                mma_bf(sf[0], ql4, kh4[0], kh4[2]);
                mma_bf(sf[1], ql4, kh4[1], kh4[3]);
            }

            if (colbase + 15 > wlim) {
                const int c0m = colbase + (lane & 3) * 2;
#pragma unroll
                for (int nt = 0; nt < 2; ++nt) {
                    const int cA = c0m + nt * 8, cB = cA + 1;
                    if (cA > lim0) sf[nt][0] = -1e30f;
                    if (cB > lim0) sf[nt][1] = -1e30f;
                    if (cA > lim1) sf[nt][2] = -1e30f;
                    if (cB > lim1) sf[nt][3] = -1e30f;
                }
            }

            float rm0 = fmaxf(fmaxf(sf[0][0], sf[0][1]), fmaxf(sf[1][0], sf[1][1]));
            float rm1 = fmaxf(fmaxf(sf[0][2], sf[0][3]), fmaxf(sf[1][2], sf[1][3]));
            rm0 = fmaxf(rm0, __shfl_xor_sync(0xffffffffu, rm0, 1));
            rm0 = fmaxf(rm0, __shfl_xor_sync(0xffffffffu, rm0, 2));
            rm1 = fmaxf(rm1, __shfl_xor_sync(0xffffffffu, rm1, 1));
            rm1 = fmaxf(rm1, __shfl_xor_sync(0xffffffffu, rm1, 2));
            const float mt0 = fmaxf(m0, rm0), mt1 = fmaxf(m1, rm1);
            const float al0 = __expf(m0 - mt0), al1 = __expf(m1 - mt1);
            m0 = mt0; m1 = mt1;

            float p[2][4];
#pragma unroll
            for (int nt = 0; nt < 2; ++nt) {
                p[nt][0] = __expf(sf[nt][0] - mt0);
                p[nt][1] = __expf(sf[nt][1] - mt0);
                p[nt][2] = __expf(sf[nt][2] - mt1);
                p[nt][3] = __expf(sf[nt][3] - mt1);
            }
            float rs0 = p[0][0] + p[0][1] + p[1][0] + p[1][1];
            float rs1 = p[0][2] + p[0][3] + p[1][2] + p[1][3];
            rs0 += __shfl_xor_sync(0xffffffffu, rs0, 1);
            rs0 += __shfl_xor_sync(0xffffffffu, rs0, 2);
            rs1 += __shfl_xor_sync(0xffffffffu, rs1, 1);
            rs1 += __shfl_xor_sync(0xffffffffu, rs1, 2);
            l0 = l0 * al0 + rs0;
            l1 = l1 * al1 + rs1;

            if (__any_sync(0xffffffffu, (al0 < 1.0f) | (al1 < 1.0f))) {
#pragma unroll
                for (int nt = 0; nt < 16; ++nt) {
                    o[nt][0] *= al0; o[nt][1] *= al0;
                    o[nt][2] *= al1; o[nt][3] *= al1;
                }
            }

            uint32_t pah[4], pal[4];
            split2(p[0][0], p[0][1], pah[0], pal[0]);
            split2(p[0][2], p[0][3], pah[1], pal[1]);
            split2(p[1][0], p[1][1], pah[2], pal[2]);
            split2(p[1][2], p[1][3], pah[3], pal[3]);

#pragma unroll
            for (int g = 0; g < 8; ++g) {
                const uint32_t va = (uint32_t)((sp * 16 + b_kr) * ARB + g * 32 + b_nb);
                uint32_t vh4[4], vl4[4];
                ldsm4t(vh4, Vhi_s + va);
                ldsm4t(vl4, Vlo_s + va);
                mma_bf(o[2 * g],     pah, vh4[0], vh4[2]);
                mma_bf(o[2 * g + 1], pah, vh4[1], vh4[3]);
                mma_bf(o[2 * g],     pah, vl4[0], vl4[2]);
                mma_bf(o[2 * g + 1], pah, vl4[1], vl4[3]);
                mma_bf(o[2 * g],     pal, vh4[0], vh4[2]);
                mma_bf(o[2 * g + 1], pal, vh4[1], vh4[3]);
            }
        }
    }

    __syncthreads();
    {
        const int r0 = lane >> 2, c0 = (lane & 3) * 2;
#pragma unroll
        for (int nt = 0; nt < 16; ++nt) {
            *(float2*)(asmem + wid * 8192 + r0 * 512 + (nt * 8 + c0) * 4) =
                make_float2(o[nt][0], o[nt][1]);
            *(float2*)(asmem + wid * 8192 + (r0 + 8) * 512 + (nt * 8 + c0) * 4) =
                make_float2(o[nt][2], o[nt][3]);
        }
        if ((lane & 3) == 0) {
            *(float2*)(asmem + 65536 + (wid * 16 + r0) * 8)     = make_float2(m0, l0);
            *(float2*)(asmem + 65536 + (wid * 16 + r0 + 8) * 8) = make_float2(m1, l1);
        }
    }
    __syncthreads();

    {
        const int row = tid >> 2;
        const int d0  = (tid & 3) * 32;
        const int mg2 = row >> 4, rr = row & 15;
        float2 ml0 = *(const float2*)(asmem + 65536 + ((2 * mg2) * 16 + rr) * 8);
        float2 ml1 = *(const float2*)(asmem + 65536 + ((2 * mg2 + 1) * 16 + rr) * 8);
        const float M = fmaxf(ml0.x, ml1.x);
        const float w0 = __expf(ml0.x - M), w1 = __expf(ml1.x - M);
        const float inv = 1.0f / (w0 * ml0.y + w1 * ml1.y);
        const float* b0 = (const float*)(asmem + (2 * mg2) * 8192 + rr * 512 + d0 * 4);
        const float* b1 = (const float*)(asmem + (2 * mg2 + 1) * 8192 + rr * 512 + d0 * 4);
        const size_t dst = (size_t)(b * L_ + q0 + row) * D_ + h * 128 + d0;
#pragma unroll
        for (int j = 0; j < 8; ++j) {
            float4 f0 = *(const float4*)(b0 + 4 * j);
            float4 f1 = *(const float4*)(b1 + 4 * j);
            float vx = (w0 * f0.x + w1 * f1.x) * inv;
            float vy = (w0 * f0.y + w1 * f1.y) * inv;
            float vz = (w0 * f0.z + w1 * f1.z) * inv;
            float vw = (w0 * f0.w + w1 * f1.w) * inv;
            uint32_t h0, lo0, h1, lo1;
            split2(vx, vy, h0, lo0);
            split2(vz, vw, h1, lo1);
            *(uint2*)(Ohi + dst + 4 * j) = make_uint2(h0, h1);
            *(uint2*)(Olo + dst + 4 * j) = make_uint2(lo0, lo1);
        }
    }
}

// ---------------------------------------------------------------------------
extern "C" void kernel_launch(void* const* d_in, const int* in_sizes, int n_in,
                              void* d_out, int out_size) {
    const float* x  = (const float*)d_in[0];
    const float* ck = (const float*)d_in[1];
    const float* cv = (const float*)d_in[2];
    const float* Wq = (const float*)d_in[3];
    const float* Wk = (const float*)d_in[4];
    const float* Wv = (const float*)d_in[5];
    const float* Wo = (const float*)d_in[6];
    const float* qw = (const float*)d_in[7];
    const float* kw = (const float*)d_in[8];
    float* out = (float*)d_out;

    void *pq, *pk, *pv, *pwh, *pwl, *pxh, *pxl, *poh, *pol;
    void *pckh, *pckl, *pcvh, *pcvl, *pnkh, *pnkl, *pnvh, *pnvl;
    cudaGetSymbolAddress(&pq, g_q);
    cudaGetSymbolAddress(&pk, g_k);
    cudaGetSymbolAddress(&pv, g_v);
    cudaGetSymbolAddress(&pwh, g_whi);
    cudaGetSymbolAddress(&pwl, g_wlo);
    cudaGetSymbolAddress(&pxh, g_xhi);
    cudaGetSymbolAddress(&pxl, g_xlo);
    cudaGetSymbolAddress(&poh, g_ohi);
    cudaGetSymbolAddress(&pol, g_olo);
    cudaGetSymbolAddress(&pckh, g_ckhi);
    cudaGetSymbolAddress(&pckl, g_cklo);
    cudaGetSymbolAddress(&pcvh, g_cvhi);
    cudaGetSymbolAddress(&pcvl, g_cvlo);
    cudaGetSymbolAddress(&pnkh, g_nkhi);
    cudaGetSymbolAddress(&pnkl, g_nklo);
    cudaGetSymbolAddress(&pnvh, g_nvhi);
    cudaGetSymbolAddress(&pnvl, g_nvlo);

    float* Qb = (float*)pq;
    float* Kb = (float*)pk;
    float* Vb = (float*)pv;
    __nv_bfloat16* Whi = (__nv_bfloat16*)pwh;
    __nv_bfloat16* Wlo = (__nv_bfloat16*)pwl;
    __nv_bfloat16* Xhi = (__nv_bfloat16*)pxh;
    __nv_bfloat16* Xlo = (__nv_bfloat16*)pxl;
    __nv_bfloat16* Ohi = (__nv_bfloat16*)poh;
    __nv_bfloat16* Olo = (__nv_bfloat16*)pol;

    cudaFuncSetAttribute(gemm_mma, cudaFuncAttributeMaxDynamicSharedMemorySize, SMEMT);
    cudaFuncSetAttribute(attn_mma, cudaFuncAttributeMaxDynamicSharedMemorySize, ATT_SMEM);

    // Fully serial — overlap attempts contended (R14: +600us). Single stream.
    cvt_w<<<dim3((unsigned)(DD / 2048), 4), 256>>>(Wq, Wk, Wv, Wo, Whi, Wlo);
    cvt_x<<<(M_ * D_) / 2048, 256>>>(x, Xhi, Xlo);
    cvt_x<<<(int)(CACHE_E / 2048), 256>>>(ck, (__nv_bfloat16*)pckh, (__nv_bfloat16*)pckl);
    cvt_x<<<(int)(CACHE_E / 2048), 256>>>(cv, (__nv_bfloat16*)pcvh, (__nv_bfloat16*)pcvl);

    // QKV projection
    gemm_mma<<<dim3(D_ / 128, M_ / 128, 3), 256, SMEMT>>>(Xhi, Xlo, Whi, Wlo, 0, 0, Qb, Kb, Vb);
    rmsnorm_qsplit<<<(M_ * H_) / 8, 256>>>(Qb, qw, Xhi, Xlo);
    rmsnorm_split<<<(M_ * H_) / 8, 256>>>(Kb, kw, (__nv_bfloat16*)pnkh, (__nv_bfloat16*)pnkl);
    cvt_x<<<(M_ * D_) / 2048, 256>>>(Vb, (__nv_bfloat16*)pnvh, (__nv_bfloat16*)pnvl);

    // Attention
    attn_mma<<<dim3(L_ / 64, H_, B_), 256, ATT_SMEM>>>(
        Xhi, Xlo,
        (const __nv_bfloat16*)pckh, (const __nv_bfloat16*)pckl,
        (const __nv_bfloat16*)pcvh, (const __nv_bfloat16*)pcvl,
        (const __nv_bfloat16*)pnkh, (const __nv_bfloat16*)pnkl,
        (const __nv_bfloat16*)pnvh, (const __nv_bfloat16*)pnvl,
        Ohi, Olo);

    // Output projection: split-K=2 (Qb/Kb fp32 buffers dead — reuse as partials)
    gemm_mma<<<dim3(D_ / 128, M_ / 128, 2), 256, SMEMT>>>(Ohi, Olo, Whi, Wlo, 3, 1, Qb, Kb, Kb);
    add2<<<(M_ * D_) / 1024, 256>>>(Qb, Kb, out);
}

// round 17
// speedup vs baseline: 1.4570x; 1.4570x over previous
#include <cuda_runtime.h>
#include <cuda_bf16.h>
#include <cstdint>

// Problem constants
constexpr int B_  = 2;
constexpr int L_  = 256;
constexpr int D_  = 4096;
constexpr int H_  = 32;
constexpr int Dh_ = 128;
constexpr int S_  = 4224;
constexpr int SINK_ = 128;
constexpr int WINS_ = S_ - L_;     // 3968
constexpr int M_  = B_ * L_;       // 512
constexpr size_t DD = (size_t)D_ * D_;
constexpr size_t CACHE_E = (size_t)B_ * S_ * H_ * Dh_;

// GEMM tiling
constexpr int BK = 32;
constexpr int NCHUNK = D_ / BK;        // 128
constexpr int A_ROW_B = 80;
constexpr int B_ROW_B = 272;
constexpr int A_TILE = 128 * A_ROW_B;  // 10240
constexpr int B_TILE = BK * B_ROW_B;   // 8704
constexpr int STAGE  = 2 * A_TILE + 2 * B_TILE;  // 37888
constexpr int SMEMT  = 2 * STAGE;      // 75776

// Attention smem
constexpr int ARB = 272;
constexpr int AQ_COMP = 64 * ARB;              // 17408
constexpr int AT_COMP = 32 * ARB;              // 8704
constexpr int AT_STG  = 4 * AT_COMP;           // 34816
constexpr int ATT_SMEM = 2 * AQ_COMP + 2 * AT_STG;  // 104448

// scratch
__device__ float g_q[M_ * D_];     // Q fp32; reused as split-K partial 0
__device__ float g_k[M_ * D_];     // K fp32; reused as split-K partial 1
__device__ float g_v[M_ * D_];
__device__ __nv_bfloat16 g_whi[4 * DD];
__device__ __nv_bfloat16 g_wlo[4 * DD];
__device__ __nv_bfloat16 g_xhi[M_ * D_];   // x split; reused for Q split
__device__ __nv_bfloat16 g_xlo[M_ * D_];
__device__ __nv_bfloat16 g_ohi[M_ * D_];
__device__ __nv_bfloat16 g_olo[M_ * D_];
__device__ __nv_bfloat16 g_ckhi[CACHE_E];
__device__ __nv_bfloat16 g_cklo[CACHE_E];
__device__ __nv_bfloat16 g_cvhi[CACHE_E];
__device__ __nv_bfloat16 g_cvlo[CACHE_E];
__device__ __nv_bfloat16 g_nkhi[M_ * D_];
__device__ __nv_bfloat16 g_nklo[M_ * D_];
__device__ __nv_bfloat16 g_nvhi[M_ * D_];
__device__ __nv_bfloat16 g_nvlo[M_ * D_];

// ---- helpers ----
__device__ __forceinline__ uint32_t smem_u32(const void* p) {
    uint32_t a;
    asm("{ .reg .u64 t; cvta.to.shared.u64 t, %1; cvt.u32.u64 %0, t; }" : "=r"(a) : "l"(p));
    return a;
}
__device__ __forceinline__ void ldsm4(uint32_t* r, uint32_t a) {
    asm volatile("ldmatrix.sync.aligned.m8n8.x4.shared.b16 {%0,%1,%2,%3},[%4];"
                 : "=r"(r[0]), "=r"(r[1]), "=r"(r[2]), "=r"(r[3]) : "r"(a));
}
__device__ __forceinline__ void ldsm4t(uint32_t* r, uint32_t a) {
    asm volatile("ldmatrix.sync.aligned.m8n8.x4.trans.shared.b16 {%0,%1,%2,%3},[%4];"
                 : "=r"(r[0]), "=r"(r[1]), "=r"(r[2]), "=r"(r[3]) : "r"(a));
}
__device__ __forceinline__ void mma_bf(float* c, const uint32_t* a, uint32_t b0, uint32_t b1) {
    asm volatile(
        "mma.sync.aligned.m16n8k16.row.col.f32.bf16.bf16.f32 "
        "{%0,%1,%2,%3},{%4,%5,%6,%7},{%8,%9},{%0,%1,%2,%3};"
        : "+f"(c[0]), "+f"(c[1]), "+f"(c[2]), "+f"(c[3])
        : "r"(a[0]), "r"(a[1]), "r"(a[2]), "r"(a[3]), "r"(b0), "r"(b1));
}
// packed split: rn rounding, bit-identical to scalar __float2bfloat16_rn path.
__device__ __forceinline__ void split2(float x, float y, uint32_t& hi, uint32_t& lo) {
    uint32_t h;
    asm("cvt.rn.bf16x2.f32 %0, %1, %2;" : "=r"(h) : "f"(y), "f"(x));
    float hx = __uint_as_float(h << 16);
    float hy = __uint_as_float(h & 0xffff0000u);
    float lx = x - hx;
    float ly = y - hy;
    uint32_t l;
    asm("cvt.rn.bf16x2.f32 %0, %1, %2;" : "=r"(l) : "f"(ly), "f"(lx));
    hi = h; lo = l;
}
__device__ __forceinline__ void cpa16(uint32_t dst, const void* src) {
    asm volatile("cp.async.ca.shared.global [%0],[%1],16;" :: "r"(dst), "l"(src));
}
__device__ __forceinline__ void cpa_commit() {
    asm volatile("cp.async.commit_group;" ::: "memory");
}
__device__ __forceinline__ void cpa_wait1() {
    asm volatile("cp.async.wait_group 1;" ::: "memory");
}
__device__ __forceinline__ void cpa_wait0() {
    asm volatile("cp.async.wait_group 0;" ::: "memory");
}

// ---------------------------------------------------------------------------
// Split-convert kernels (serial execution)
// ---------------------------------------------------------------------------
__global__ __launch_bounds__(256) void cvt_x(
    const float* __restrict__ src,
    __nv_bfloat16* __restrict__ hi, __nv_bfloat16* __restrict__ lo)
{
    const size_t i = ((size_t)blockIdx.x * 256 + threadIdx.x) * 8;
    float4 f0 = *(const float4*)(src + i);
    float4 f1 = *(const float4*)(src + i + 4);
    uint4 h, l;
    split2(f0.x, f0.y, h.x, l.x);
    split2(f0.z, f0.w, h.y, l.y);
    split2(f1.x, f1.y, h.z, l.z);
    split2(f1.z, f1.w, h.w, l.w);
    *(uint4*)(hi + i) = h;
    *(uint4*)(lo + i) = l;
}

__global__ __launch_bounds__(256) void cvt_w(
    const float* __restrict__ w0, const float* __restrict__ w1,
    const float* __restrict__ w2, const float* __restrict__ w3,
    __nv_bfloat16* __restrict__ hi, __nv_bfloat16* __restrict__ lo)
{
    const float* src = (blockIdx.y == 0) ? w0 : (blockIdx.y == 1) ? w1
                     : (blockIdx.y == 2) ? w2 : w3;
    const size_t base = (size_t)blockIdx.y * DD;
    const size_t i = ((size_t)blockIdx.x * 256 + threadIdx.x) * 8;
    float4 f0 = *(const float4*)(src + i);
    float4 f1 = *(const float4*)(src + i + 4);
    uint4 h, l;
    split2(f0.x, f0.y, h.x, l.x);
    split2(f0.z, f0.w, h.y, l.y);
    split2(f1.x, f1.y, h.z, l.z);
    split2(f1.z, f1.w, h.w, l.w);
    *(uint4*)(hi + base + i) = h;
    *(uint4*)(lo + base + i) = l;
}

// out = a + b (fp32, vectorized) — split-K reduction
__global__ __launch_bounds__(256) void add2(const float* __restrict__ a,
                                            const float* __restrict__ b,
                                            float* __restrict__ out) {
    const size_t i = ((size_t)blockIdx.x * 256 + threadIdx.x) * 4;
    float4 x = *(const float4*)(a + i);
    float4 y = *(const float4*)(b + i);
    *(float4*)(out + i) = make_float4(x.x + y.x, x.y + y.y, x.z + y.z, x.w + y.w);
}

// ---------------------------------------------------------------------------
// mma.sync split-bf16 GEMM — TEMPLATED on SPLITK so the full-K instantiation
// stays bit-identical to the proven R12 kernel (R14's runtime splitk param
// pushed regs past the 128 cap -> hot-loop spills -> +600us on both GEMMs).
// SPLITK=0: blockIdx.z selects (weight, C); full K.
// SPLITK=1: weight fixed at wzoff; blockIdx.z selects K-half; C0/C1 partials.
// ---------------------------------------------------------------------------
template <int SPLITK>
__global__ __launch_bounds__(256, 2) void gemm_mma(
    const __nv_bfloat16* __restrict__ Ahi, const __nv_bfloat16* __restrict__ Alo,
    const __nv_bfloat16* __restrict__ Whi, const __nv_bfloat16* __restrict__ Wlo,
    int wzoff,
    float* __restrict__ C0, float* __restrict__ C1, float* __restrict__ C2)
{
    const int z = blockIdx.z;
    float* C = (z == 0) ? C0 : (z == 1) ? C1 : C2;
    const size_t woff = (size_t)(SPLITK ? wzoff : wzoff + z) * DD;
    const int kbeg = SPLITK ? z * (NCHUNK / 2) : 0;
    constexpr int NCH = SPLITK ? (NCHUNK / 2) : NCHUNK;

    extern __shared__ char smem[];
    const uint32_t sb = smem_u32(smem);
    const int tid  = threadIdx.x;
    const int wid  = tid >> 5;
    const int lane = tid & 31;
    const int wm   = wid & 1;
    const int wn   = wid >> 1;

    const int m0 = blockIdx.y * 128;
    const int n0 = blockIdx.x * 128;

    const __nv_bfloat16* AhiB = Ahi + (size_t)m0 * D_;
    const __nv_bfloat16* AloB = Alo + (size_t)m0 * D_;
    const __nv_bfloat16* WhiB = Whi + woff + n0;
    const __nv_bfloat16* WloB = Wlo + woff + n0;

    float acc[4][4][4];
#pragma unroll
    for (int mt = 0; mt < 4; ++mt)
#pragma unroll
        for (int nt = 0; nt < 4; ++nt)
#pragma unroll
            for (int e = 0; e < 4; ++e) acc[mt][nt][e] = 0.0f;

    const int a_r   = (lane & 7) + ((lane >> 3) & 1) * 8;
    const int a_kb  = (lane >> 4) * 16;
    const int b_kr  = (lane & 7) + (lane >> 4) * 8;
    const int b_nb  = ((lane >> 3) & 1) * 16;

    auto issue_stage = [&](int ch, int s) {
        const uint32_t stA = sb + s * STAGE;
        const uint32_t stB = stA + 2 * A_TILE;
#pragma unroll
        for (int i = 0; i < 2; ++i) {
            const int c = tid * 2 + i;
            const int ar = c >> 2, akc = c & 3;
            const size_t aoff = (size_t)ar * D_ + ch * BK + akc * 8;
            const uint32_t adst = stA + ar * A_ROW_B + akc * 16;
            cpa16(adst, AhiB + aoff);
            cpa16(adst + A_TILE, AloB + aoff);
            const int br = c >> 4, bnc = c & 15;
            const size_t boff = (size_t)(ch * BK + br) * D_ + bnc * 8;
            const uint32_t bdst = stB + br * B_ROW_B + bnc * 16;
            cpa16(bdst, WhiB + boff);
            cpa16(bdst + B_TILE, WloB + boff);
        }
        cpa_commit();
    };

    issue_stage(kbeg, 0);

    for (int ci = 0; ci < NCH; ++ci) {
        const int s = ci & 1;
        if (ci + 1 < NCH) { issue_stage(kbeg + ci + 1, s ^ 1); cpa_wait1(); }
        else cpa_wait0();
        __syncthreads();

        const uint32_t Ah = sb + s * STAGE;
        const uint32_t Al = Ah + A_TILE;
        const uint32_t Bh = Ah + 2 * A_TILE;
        const uint32_t Bl = Bh + B_TILE;

#pragma unroll
        for (int kc = 0; kc < 2; ++kc) {
            uint32_t ah[4][4], al[4][4];
            uint32_t bh[4][2], bl[4][2];
            const uint32_t a_addr = (uint32_t)((wm * 64 + a_r) * A_ROW_B + kc * 32 + a_kb);
#pragma unroll
            for (int mt = 0; mt < 4; ++mt) {
                ldsm4(ah[mt], Ah + a_addr + mt * 16 * A_ROW_B);
                ldsm4(al[mt], Al + a_addr + mt * 16 * A_ROW_B);
            }
            const uint32_t b_addr = (uint32_t)((kc * 16 + b_kr) * B_ROW_B + (wn * 32) * 2 + b_nb);
#pragma unroll
            for (int p = 0; p < 2; ++p) {
                uint32_t rh[4], rl[4];
                ldsm4t(rh, Bh + b_addr + p * 32);
                ldsm4t(rl, Bl + b_addr + p * 32);
                bh[2 * p][0] = rh[0]; bh[2 * p][1] = rh[2];
                bh[2 * p + 1][0] = rh[1]; bh[2 * p + 1][1] = rh[3];
                bl[2 * p][0] = rl[0]; bl[2 * p][1] = rl[2];
                bl[2 * p + 1][0] = rl[1]; bl[2 * p + 1][1] = rl[3];
            }
#pragma unroll
            for (int mt = 0; mt < 4; ++mt)
#pragma unroll
                for (int nt = 0; nt < 4; ++nt)
                    mma_bf(acc[mt][nt], ah[mt], bh[nt][0], bh[nt][1]);
#pragma unroll
            for (int mt = 0; mt < 4; ++mt)
#pragma unroll
                for (int nt = 0; nt < 4; ++nt)
                    mma_bf(acc[mt][nt], ah[mt], bl[nt][0], bl[nt][1]);
#pragma unroll
            for (int mt = 0; mt < 4; ++mt)
#pragma unroll
                for (int nt = 0; nt < 4; ++nt)
                    mma_bf(acc[mt][nt], al[mt], bh[nt][0], bh[nt][1]);
        }
        __syncthreads();
    }

    const int gr = lane >> 2;
    const int gc = lane & 3;
#pragma unroll
    for (int mt = 0; mt < 4; ++mt) {
        const int row = m0 + wm * 64 + mt * 16 + gr;
        float* c0 = C + (size_t)row * D_ + n0 + wn * 32;
        float* c1 = C + (size_t)(row + 8) * D_ + n0 + wn * 32;
#pragma unroll
        for (int nt = 0; nt < 4; ++nt) {
            *(float2*)(c0 + nt * 8 + gc * 2) = make_float2(acc[mt][nt][0], acc[mt][nt][1]);
            *(float2*)(c1 + nt * 8 + gc * 2) = make_float2(acc[mt][nt][2], acc[mt][nt][3]);
        }
    }
}

// ---------------------------------------------------------------------------
// rmsnorm + split + pre-scale (Q)
// ---------------------------------------------------------------------------
__global__ __launch_bounds__(256) void rmsnorm_qsplit(const float* __restrict__ X,
                                                      const float* __restrict__ w,
                                                      __nv_bfloat16* __restrict__ hi,
                                                      __nv_bfloat16* __restrict__ lo) {
    const int row  = (blockIdx.x * 256 + threadIdx.x) >> 5;
    const int lane = threadIdx.x & 31;
    const float* p = X + (size_t)row * 128 + lane * 4;
    float4 v = *(const float4*)p;
    float ss = v.x * v.x + v.y * v.y + v.z * v.z + v.w * v.w;
#pragma unroll
    for (int o = 16; o; o >>= 1) ss += __shfl_xor_sync(0xffffffffu, ss, o);
    float r = rsqrtf(ss * (1.0f / 128.0f) + 1e-6f) * 0.08838834764831845f;
    float4 wv = *(const float4*)(w + lane * 4);
    v.x *= r * wv.x; v.y *= r * wv.y; v.z *= r * wv.z; v.w *= r * wv.w;
    uint32_t h0, l0, h1, l1;
    split2(v.x, v.y, h0, l0);
    split2(v.z, v.w, h1, l1);
    *(uint2*)(hi + (size_t)row * 128 + lane * 4) = make_uint2(h0, h1);
    *(uint2*)(lo + (size_t)row * 128 + lane * 4) = make_uint2(l0, l1);
}

// rmsnorm + split (K)
__global__ __launch_bounds__(256) void rmsnorm_split(const float* __restrict__ X,
                                                     const float* __restrict__ w,
                                                     __nv_bfloat16* __restrict__ hi,
                                                     __nv_bfloat16* __restrict__ lo) {
    const int row  = (blockIdx.x * 256 + threadIdx.x) >> 5;
    const int lane = threadIdx.x & 31;
    const float* p = X + (size_t)row * 128 + lane * 4;
    float4 v = *(const float4*)p;
    float ss = v.x * v.x + v.y * v.y + v.z * v.z + v.w * v.w;
#pragma unroll
    for (int o = 16; o; o >>= 1) ss += __shfl_xor_sync(0xffffffffu, ss, o);
    float r = rsqrtf(ss * (1.0f / 128.0f) + 1e-6f);
    float4 wv = *(const float4*)(w + lane * 4);
    v.x *= r * wv.x; v.y *= r * wv.y; v.z *= r * wv.z; v.w *= r * wv.w;
    uint32_t h0, l0, h1, l1;
    split2(v.x, v.y, h0, l0);
    split2(v.z, v.w, h1, l1);
    *(uint2*)(hi + (size_t)row * 128 + lane * 4) = make_uint2(h0, h1);
    *(uint2*)(lo + (size_t)row * 128 + lane * 4) = make_uint2(l0, l1);
}

// ---------------------------------------------------------------------------
// MMA flash attention (unchanged from R13)
// ---------------------------------------------------------------------------
__global__ __launch_bounds__(256, 2) void attn_mma(
    const __nv_bfloat16* __restrict__ Qhi, const __nv_bfloat16* __restrict__ Qlo,
    const __nv_bfloat16* __restrict__ CKhi, const __nv_bfloat16* __restrict__ CKlo,
    const __nv_bfloat16* __restrict__ CVhi, const __nv_bfloat16* __restrict__ CVlo,
    const __nv_bfloat16* __restrict__ NKhi, const __nv_bfloat16* __restrict__ NKlo,
    const __nv_bfloat16* __restrict__ NVhi, const __nv_bfloat16* __restrict__ NVlo,
    __nv_bfloat16* __restrict__ Ohi, __nv_bfloat16* __restrict__ Olo)
{
    extern __shared__ char asmem[];
    const uint32_t sb = smem_u32(asmem);

    const int tid  = threadIdx.x;
    const int wid  = tid >> 5;
    const int lane = tid & 31;
    const int mg   = wid >> 1;
    const int sp   = wid & 1;
    const int h    = blockIdx.y;
    const int b    = blockIdx.z;
    const int q0   = blockIdx.x * 64;

    const uint32_t Qhi_o = sb;
    const uint32_t Qlo_o = sb + AQ_COMP;
    const uint32_t STG0  = sb + 2 * AQ_COMP;

    {
        const int row = tid >> 2;
        const int d0  = (tid & 3) * 32;
        const size_t src = ((size_t)(b * L_ + q0 + row) * H_ + h) * Dh_ + d0;
        const uint32_t dst = (uint32_t)(row * ARB + d0 * 2);
#pragma unroll
        for (int i = 0; i < 4; ++i) {
            cpa16(Qhi_o + dst + 16 * i, Qhi + src + 8 * i);
            cpa16(Qlo_o + dst + 16 * i, Qlo + src + 8 * i);
        }
    }

    const int a_r  = (lane & 7) + ((lane >> 3) & 1) * 8;
    const int a_kb = (lane >> 4) * 16;
    const int b_kr = (lane & 7) + (lane >> 4) * 8;
    const int b_nb = ((lane >> 3) & 1) * 16;

    float o[16][4];
#pragma unroll
    for (int nt = 0; nt < 16; ++nt)
#pragma unroll
        for (int e = 0; e < 4; ++e) o[nt][e] = 0.0f;
    float m0 = -1e30f, m1 = -1e30f, l0 = 0.0f, l1 = 0.0f;

    const int wlim = WINS_ + q0 + mg * 16;
    const int lim0 = wlim + (lane >> 2);
    const int lim1 = lim0 + 8;
    const int n_t  = (WINS_ + q0 + 64) / 32;

    auto issue_tile = [&](int t, int s) {
        const int sg = t * 32 + (tid >> 3);
        const __nv_bfloat16 *kh, *kl, *vh, *vl;
        if (sg < WINS_) {
            const int src = (sg < SINK_) ? sg : sg + L_;
            const size_t off = (((size_t)b * S_ + src) * H_ + h) * Dh_;
            kh = CKhi + off; kl = CKlo + off; vh = CVhi + off; vl = CVlo + off;
        } else {
            const size_t off = (((size_t)b * L_ + (sg - WINS_)) * H_ + h) * Dh_;
            kh = NKhi + off; kl = NKlo + off; vh = NVhi + off; vl = NVlo + off;
        }
        const uint32_t base = STG0 + s * AT_STG + (tid >> 3) * ARB;
#pragma unroll
        for (int i = 0; i < 2; ++i) {
            const int c16 = (tid & 7) * 2 + i;
            const uint32_t d = base + c16 * 16;
            cpa16(d, kh + c16 * 8);
            cpa16(d + AT_COMP, kl + c16 * 8);
            cpa16(d + 2 * AT_COMP, vh + c16 * 8);
            cpa16(d + 3 * AT_COMP, vl + c16 * 8);
        }
        cpa_commit();
    };

    issue_tile(0, 0);

    for (int t = 0; t < n_t; ++t) {
        const int s = t & 1;
        cpa_wait0();
        __syncthreads();
        if (t + 1 < n_t) issue_tile(t + 1, s ^ 1);

        const int colbase = t * 32 + sp * 16;
        if (colbase <= wlim + 15) {
            const uint32_t Khi_s = STG0 + s * AT_STG;
            const uint32_t Klo_s = Khi_s + AT_COMP;
            const uint32_t Vhi_s = Khi_s + 2 * AT_COMP;
            const uint32_t Vlo_s = Khi_s + 3 * AT_COMP;

            float sf[2][4];
#pragma unroll
            for (int nt = 0; nt < 2; ++nt)
#pragma unroll
                for (int e = 0; e < 4; ++e) sf[nt][e] = 0.0f;

#pragma unroll
            for (int ks = 0; ks < 8; ++ks) {
                const uint32_t qa = (uint32_t)((mg * 16 + a_r) * ARB + ks * 32 + a_kb);
                const uint32_t ka = (uint32_t)((sp * 16 + a_r) * ARB + ks * 32 + a_kb);
                uint32_t qh4[4], ql4[4], kh4[4], kl4[4];
                ldsm4(qh4, Qhi_o + qa);
                ldsm4(ql4, Qlo_o + qa);
                ldsm4(kh4, Khi_s + ka);
                ldsm4(kl4, Klo_s + ka);
                mma_bf(sf[0], qh4, kh4[0], kh4[2]);
                mma_bf(sf[1], qh4, kh4[1], kh4[3]);
                mma_bf(sf[0], qh4, kl4[0], kl4[2]);
                mma_bf(sf[1], qh4, kl4[1], kl4[3]);
                mma_bf(sf[0], ql4, kh4[0], kh4[2]);
                mma_bf(sf[1], ql4, kh4[1], kh4[3]);
            }

            if (colbase + 15 > wlim) {
                const int c0m = colbase + (lane & 3) * 2;
#pragma unroll
                for (int nt = 0; nt < 2; ++nt) {
                    const int cA = c0m + nt * 8, cB = cA + 1;
                    if (cA > lim0) sf[nt][0] = -1e30f;
                    if (cB > lim0) sf[nt][1] = -1e30f;
                    if (cA > lim1) sf[nt][2] = -1e30f;
                    if (cB > lim1) sf[nt][3] = -1e30f;
                }
            }

            float rm0 = fmaxf(fmaxf(sf[0][0], sf[0][1]), fmaxf(sf[1][0], sf[1][1]));
            float rm1 = fmaxf(fmaxf(sf[0][2], sf[0][3]), fmaxf(sf[1][2], sf[1][3]));
            rm0 = fmaxf(rm0, __shfl_xor_sync(0xffffffffu, rm0, 1));
            rm0 = fmaxf(rm0, __shfl_xor_sync(0xffffffffu, rm0, 2));
            rm1 = fmaxf(rm1, __shfl_xor_sync(0xffffffffu, rm1, 1));
            rm1 = fmaxf(rm1, __shfl_xor_sync(0xffffffffu, rm1, 2));
            const float mt0 = fmaxf(m0, rm0), mt1 = fmaxf(m1, rm1);
            const float al0 = __expf(m0 - mt0), al1 = __expf(m1 - mt1);
            m0 = mt0; m1 = mt1;

            float p[2][4];
#pragma unroll
            for (int nt = 0; nt < 2; ++nt) {
                p[nt][0] = __expf(sf[nt][0] - mt0);
                p[nt][1] = __expf(sf[nt][1] - mt0);
                p[nt][2] = __expf(sf[nt][2] - mt1);
                p[nt][3] = __expf(sf[nt][3] - mt1);
            }
            float rs0 = p[0][0] + p[0][1] + p[1][0] + p[1][1];
            float rs1 = p[0][2] + p[0][3] + p[1][2] + p[1][3];
            rs0 += __shfl_xor_sync(0xffffffffu, rs0, 1);
            rs0 += __shfl_xor_sync(0xffffffffu, rs0, 2);
            rs1 += __shfl_xor_sync(0xffffffffu, rs1, 1);
            rs1 += __shfl_xor_sync(0xffffffffu, rs1, 2);
            l0 = l0 * al0 + rs0;
            l1 = l1 * al1 + rs1;

            if (__any_sync(0xffffffffu, (al0 < 1.0f) | (al1 < 1.0f))) {
#pragma unroll
                for (int nt = 0; nt < 16; ++nt) {
                    o[nt][0] *= al0; o[nt][1] *= al0;
                    o[nt][2] *= al1; o[nt][3] *= al1;
                }
            }

            uint32_t pah[4], pal[4];
            split2(p[0][0], p[0][1], pah[0], pal[0]);
            split2(p[0][2], p[0][3], pah[1], pal[1]);
            split2(p[1][0], p[1][1], pah[2], pal[2]);
            split2(p[1][2], p[1][3], pah[3], pal[3]);

#pragma unroll
            for (int g = 0; g < 8; ++g) {
                const uint32_t va = (uint32_t)((sp * 16 + b_kr) * ARB + g * 32 + b_nb);
                uint32_t vh4[4], vl4[4];
                ldsm4t(vh4, Vhi_s + va);
                ldsm4t(vl4, Vlo_s + va);
                mma_bf(o[2 * g],     pah, vh4[0], vh4[2]);
                mma_bf(o[2 * g + 1], pah, vh4[1], vh4[3]);
                mma_bf(o[2 * g],     pah, vl4[0], vl4[2]);
                mma_bf(o[2 * g + 1], pah, vl4[1], vl4[3]);
                mma_bf(o[2 * g],     pal, vh4[0], vh4[2]);
                mma_bf(o[2 * g + 1], pal, vh4[1], vh4[3]);
            }
        }
    }

    __syncthreads();
    {
        const int r0 = lane >> 2, c0 = (lane & 3) * 2;
#pragma unroll
        for (int nt = 0; nt < 16; ++nt) {
            *(float2*)(asmem + wid * 8192 + r0 * 512 + (nt * 8 + c0) * 4) =
                make_float2(o[nt][0], o[nt][1]);
            *(float2*)(asmem + wid * 8192 + (r0 + 8) * 512 + (nt * 8 + c0) * 4) =
                make_float2(o[nt][2], o[nt][3]);
        }
        if ((lane & 3) == 0) {
            *(float2*)(asmem + 65536 + (wid * 16 + r0) * 8)     = make_float2(m0, l0);
            *(float2*)(asmem + 65536 + (wid * 16 + r0 + 8) * 8) = make_float2(m1, l1);
        }
    }
    __syncthreads();

    {
        const int row = tid >> 2;
        const int d0  = (tid & 3) * 32;
        const int mg2 = row >> 4, rr = row & 15;
        float2 ml0 = *(const float2*)(asmem + 65536 + ((2 * mg2) * 16 + rr) * 8);
        float2 ml1 = *(const float2*)(asmem + 65536 + ((2 * mg2 + 1) * 16 + rr) * 8);
        const float M = fmaxf(ml0.x, ml1.x);
        const float w0 = __expf(ml0.x - M), w1 = __expf(ml1.x - M);
        const float inv = 1.0f / (w0 * ml0.y + w1 * ml1.y);
        const float* b0 = (const float*)(asmem + (2 * mg2) * 8192 + rr * 512 + d0 * 4);
        const float* b1 = (const float*)(asmem + (2 * mg2 + 1) * 8192 + rr * 512 + d0 * 4);
        const size_t dst = (size_t)(b * L_ + q0 + row) * D_ + h * 128 + d0;
#pragma unroll
        for (int j = 0; j < 8; ++j) {
            float4 f0 = *(const float4*)(b0 + 4 * j);
            float4 f1 = *(const float4*)(b1 + 4 * j);
            float vx = (w0 * f0.x + w1 * f1.x) * inv;
            float vy = (w0 * f0.y + w1 * f1.y) * inv;
            float vz = (w0 * f0.z + w1 * f1.z) * inv;
            float vw = (w0 * f0.w + w1 * f1.w) * inv;
            uint32_t h0, lo0, h1, lo1;
            split2(vx, vy, h0, lo0);
            split2(vz, vw, h1, lo1);
            *(uint2*)(Ohi + dst + 4 * j) = make_uint2(h0, h1);
            *(uint2*)(Olo + dst + 4 * j) = make_uint2(lo0, lo1);
        }
    }
}

// ---------------------------------------------------------------------------
extern "C" void kernel_launch(void* const* d_in, const int* in_sizes, int n_in,
                              void* d_out, int out_size) {
    const float* x  = (const float*)d_in[0];
    const float* ck = (const float*)d_in[1];
    const float* cv = (const float*)d_in[2];
    const float* Wq = (const float*)d_in[3];
    const float* Wk = (const float*)d_in[4];
    const float* Wv = (const float*)d_in[5];
    const float* Wo = (const float*)d_in[6];
    const float* qw = (const float*)d_in[7];
    const float* kw = (const float*)d_in[8];
    float* out = (float*)d_out;

    void *pq, *pk, *pv, *pwh, *pwl, *pxh, *pxl, *poh, *pol;
    void *pckh, *pckl, *pcvh, *pcvl, *pnkh, *pnkl, *pnvh, *pnvl;
    cudaGetSymbolAddress(&pq, g_q);
    cudaGetSymbolAddress(&pk, g_k);
    cudaGetSymbolAddress(&pv, g_v);
    cudaGetSymbolAddress(&pwh, g_whi);
    cudaGetSymbolAddress(&pwl, g_wlo);
    cudaGetSymbolAddress(&pxh, g_xhi);
    cudaGetSymbolAddress(&pxl, g_xlo);
    cudaGetSymbolAddress(&poh, g_ohi);
    cudaGetSymbolAddress(&pol, g_olo);
    cudaGetSymbolAddress(&pckh, g_ckhi);
    cudaGetSymbolAddress(&pckl, g_cklo);
    cudaGetSymbolAddress(&pcvh, g_cvhi);
    cudaGetSymbolAddress(&pcvl, g_cvlo);
    cudaGetSymbolAddress(&pnkh, g_nkhi);
    cudaGetSymbolAddress(&pnkl, g_nklo);
    cudaGetSymbolAddress(&pnvh, g_nvhi);
    cudaGetSymbolAddress(&pnvl, g_nvlo);

    float* Qb = (float*)pq;
    float* Kb = (float*)pk;
    float* Vb = (float*)pv;
    __nv_bfloat16* Whi = (__nv_bfloat16*)pwh;
    __nv_bfloat16* Wlo = (__nv_bfloat16*)pwl;
    __nv_bfloat16* Xhi = (__nv_bfloat16*)pxh;
    __nv_bfloat16* Xlo = (__nv_bfloat16*)pxl;
    __nv_bfloat16* Ohi = (__nv_bfloat16*)poh;
    __nv_bfloat16* Olo = (__nv_bfloat16*)pol;

    cudaFuncSetAttribute(gemm_mma<0>, cudaFuncAttributeMaxDynamicSharedMemorySize, SMEMT);
    cudaFuncSetAttribute(gemm_mma<1>, cudaFuncAttributeMaxDynamicSharedMemorySize, SMEMT);
    cudaFuncSetAttribute(attn_mma, cudaFuncAttributeMaxDynamicSharedMemorySize, ATT_SMEM);

    // Fully serial, single stream.
    cvt_w<<<dim3((unsigned)(DD / 2048), 4), 256>>>(Wq, Wk, Wv, Wo, Whi, Wlo);
    cvt_x<<<(M_ * D_) / 2048, 256>>>(x, Xhi, Xlo);
    cvt_x<<<(int)(CACHE_E / 2048), 256>>>(ck, (__nv_bfloat16*)pckh, (__nv_bfloat16*)pckl);
    cvt_x<<<(int)(CACHE_E / 2048), 256>>>(cv, (__nv_bfloat16*)pcvh, (__nv_bfloat16*)pcvl);

    // QKV projection (full-K instantiation — identical codegen to R12 kernel)
    gemm_mma<0><<<dim3(D_ / 128, M_ / 128, 3), 256, SMEMT>>>(Xhi, Xlo, Whi, Wlo, 0, Qb, Kb, Vb);
    rmsnorm_qsplit<<<(M_ * H_) / 8, 256>>>(Qb, qw, Xhi, Xlo);
    rmsnorm_split<<<(M_ * H_) / 8, 256>>>(Kb, kw, (__nv_bfloat16*)pnkh, (__nv_bfloat16*)pnkl);
    cvt_x<<<(M_ * D_) / 2048, 256>>>(Vb, (__nv_bfloat16*)pnvh, (__nv_bfloat16*)pnvl);

    // Attention
    attn_mma<<<dim3(L_ / 64, H_, B_), 256, ATT_SMEM>>>(
        Xhi, Xlo,
        (const __nv_bfloat16*)pckh, (const __nv_bfloat16*)pckl,
        (const __nv_bfloat16*)pcvh, (const __nv_bfloat16*)pcvl,
        (const __nv_bfloat16*)pnkh, (const __nv_bfloat16*)pnkl,
        (const __nv_bfloat16*)pnvh, (const __nv_bfloat16*)pnvl,
        Ohi, Olo);

    // Output projection: split-K=2 instantiation (Qb/Kb dead — reuse as partials)
    gemm_mma<1><<<dim3(D_ / 128, M_ / 128, 2), 256, SMEMT>>>(Ohi, Olo, Whi, Wlo, 3, Qb, Kb, Kb);
    add2<<<(M_ * D_) / 1024, 256>>>(Qb, Kb, out);
}